// round 8
// baseline (speedup 1.0000x reference)
#include <cuda_runtime.h>
#include <math.h>

#define BB 256
#define TT 512
#define NN 128
#define GO_IDX 1
#define EOS_IDX 2
#define NEGV -10000.0f
#define NSM 148

// __device__ global scratch
__device__ float  g_alpha[BB * TT * NN];  // entering alpha rows (bit-exact)
__device__ float  g_mv[BB * TT * NN];     // pre-unary max rows
__device__ float2 g_mls[BB * TT];         // per-row {max, log-sum-exp}
__device__ int    g_assign[BB];
__device__ int    g_len[BB];
__device__ int    g_btag[BB];

// ---------------- kernel A: per-row softmax stats ----------------
__global__ __launch_bounds__(256)
void softmax_pre(const float* __restrict__ unaries)
{
    int r = blockIdx.x * 8 + (threadIdx.x >> 5);
    int lane = threadIdx.x & 31;
    const float4* u = (const float4*)(unaries + (size_t)r * NN);
    float4 x = u[lane];
    float m = fmaxf(fmaxf(x.x, x.y), fmaxf(x.z, x.w));
    #pragma unroll
    for (int o = 16; o > 0; o >>= 1) m = fmaxf(m, __shfl_xor_sync(0xffffffffu, m, o));
    float e = expf(x.x - m) + expf(x.y - m) + expf(x.z - m) + expf(x.w - m);
    #pragma unroll
    for (int o = 16; o > 0; o >>= 1) e += __shfl_xor_sync(0xffffffffu, e, o);
    if (lane == 0) g_mls[r] = make_float2(m, logf(e));
}

// ---------------- kernel B: lengths + LPT pairing ----------------
__global__ __launch_bounds__(256)
void prep_assign(const void* __restrict__ lengths_raw)
{
    __shared__ long long key[BB];
    int tid = threadIdx.x;
    const int* li = (const int*)lengths_raw;
    int len = (li[1] == 0) ? (int)(((const long long*)lengths_raw)[tid]) : li[tid];
    len = max(1, min(TT, len));
    g_len[tid] = len;
    key[tid] = ((long long)len << 32) | (long long)tid;
    __syncthreads();
    for (int k = 2; k <= BB; k <<= 1) {
        for (int jj = k >> 1; jj > 0; jj >>= 1) {
            int ixj = tid ^ jj;
            if (ixj > tid) {
                long long a = key[tid], c = key[ixj];
                bool desc = ((tid & k) == 0);
                if (desc ? (a < c) : (a > c)) { key[tid] = c; key[ixj] = a; }
            }
            __syncthreads();
        }
    }
    int rank = (tid < NSM) ? tid : (NSM + BB - 1 - tid);  // bid k+148 pairs rank 255-k
    rank = min(BB - 1, max(0, rank));
    g_assign[tid] = (int)(key[rank] & 0xffffffffLL);
}

// ---------------- kernel C: max-only forward, 2-j blocking, 1 barrier ----------------
// smem: ts 64KB | mls 4KB | bufA 512 | bufB 512 | termv 512
#define FW_SMEM (65536 + 4096 + 512 + 512 + 512)

__global__ __launch_bounds__(256, 2)
void viterbi_fwd(const float* __restrict__ unaries,
                 const float* __restrict__ trans,
                 float* __restrict__ out)
{
    extern __shared__ unsigned char sm[];
    float*  ts    = (float*)sm;                       // NN*NN
    float2* mlsS  = (float2*)(sm + 65536);            // TT
    float*  bufA  = (float*)(sm + 65536 + 4096);      // NN
    float*  bufB  = bufA + NN;                        // NN
    float*  termv = bufB + NN;                        // NN

    int b = g_assign[blockIdx.x];
    b = min(BB - 1, max(0, b));
    const int tid = threadIdx.x;
    const int q  = tid & 3;          // prev quarter (32 prev each)
    const int jj = tid >> 2;         // 0..63
    const int j0 = jj, j1 = jj + 64;
    const int len = g_len[b];

    for (int idx = tid; idx < NN * NN; idx += 256) ts[idx] = trans[idx];
    for (int idx = tid; idx < TT; idx += 256) mlsS[idx] = g_mls[b * TT + idx];
    if (tid < NN) bufA[tid] = (tid == GO_IDX) ? 0.0f : NEGV;  // exact log_softmax identity
    __syncthreads();

    float tr0[32], tr1[32];
    {
        const float4* b0 = (const float4*)(ts + j0 * NN + (q << 5));
        const float4* b1 = (const float4*)(ts + j1 * NN + (q << 5));
        #pragma unroll
        for (int k = 0; k < 8; ++k) {
            float4 v = b0[k];
            tr0[4*k+0] = v.x; tr0[4*k+1] = v.y; tr0[4*k+2] = v.z; tr0[4*k+3] = v.w;
            float4 w = b1[k];
            tr1[4*k+0] = w.x; tr1[4*k+1] = w.y; tr1[4*k+2] = w.z; tr1[4*k+3] = w.w;
        }
    }

    const float* ub = unaries + (size_t)b * TT * NN;
    const float BIG = -3.402823466e38f;
    const int  ju    = (q & 1) ? j1 : j0;   // unary column this thread prefetches
    const bool needu = (q < 2);

    float pa0 = (j0 == GO_IDX) ? 0.0f : NEGV;   // entering alpha j0 (tracked by q0)
    float pa1 = NEGV;                            // j1 >= 64 is never GO
    float ucur = needu ? ub[ju] : 0.0f;

    float* rd = bufA;
    float* wr = bufB;

    for (int t = 0; t < len; ++t) {
        float unext = 0.0f;
        if (needu && t + 1 < len) unext = ub[(t + 1) * NN + ju];

        const float4* ap4 = (const float4*)(rd + (q << 5));
        float a0c[4], a1c[4];
        #pragma unroll
        for (int c = 0; c < 4; ++c) { a0c[c] = BIG; a1c[c] = BIG; }
        #pragma unroll
        for (int k = 0; k < 8; ++k) {
            float4 a = ap4[k];                 // one LDS.128 feeds both j rows
            const int c = k & 3;
            float x0 = fmaxf(fmaxf(a.x + tr0[4*k+0], a.y + tr0[4*k+1]),
                             fmaxf(a.z + tr0[4*k+2], a.w + tr0[4*k+3]));
            float x1 = fmaxf(fmaxf(a.x + tr1[4*k+0], a.y + tr1[4*k+1]),
                             fmaxf(a.z + tr1[4*k+2], a.w + tr1[4*k+3]));
            a0c[c] = fmaxf(a0c[c], x0);
            a1c[c] = fmaxf(a1c[c], x1);
        }
        float bv0 = fmaxf(fmaxf(a0c[0], a0c[1]), fmaxf(a0c[2], a0c[3]));
        float bv1 = fmaxf(fmaxf(a1c[0], a1c[1]), fmaxf(a1c[2], a1c[3]));
        bv0 = fmaxf(bv0, __shfl_xor_sync(0xffffffffu, bv0, 1));
        bv0 = fmaxf(bv0, __shfl_xor_sync(0xffffffffu, bv0, 2));
        bv1 = fmaxf(bv1, __shfl_xor_sync(0xffffffffu, bv1, 1));
        bv1 = fmaxf(bv1, __shfl_xor_sync(0xffffffffu, bv1, 2));

        const size_t rowo = ((size_t)b * TT + t) * NN;
        float2 c2 = mlsS[t];
        if (q == 0) {
            float na = bv0 + ((ucur - c2.x) - c2.y);
            wr[j0] = na; g_alpha[rowo + j0] = pa0; pa0 = na;
        } else if (q == 1) {
            float na = bv1 + ((ucur - c2.x) - c2.y);
            wr[j1] = na; g_alpha[rowo + j1] = pa1; pa1 = na;
        } else if (q == 2) {
            g_mv[rowo + j0] = bv0;
        } else {
            g_mv[rowo + j1] = bv1;
        }
        ucur = unext;
        float* tmp = rd; rd = wr; wr = tmp;
        __syncthreads();
    }

    // terminal
    if (tid < NN) termv[tid] = rd[tid] + ts[EOS_IDX * NN + tid];
    __syncthreads();
    if (tid == 0) {
        float bvv = termv[0]; int bi = 0;
        #pragma unroll 4
        for (int p = 1; p < NN; ++p)
            if (termv[p] > bvv) { bvv = termv[p]; bi = p; }   // strict > : first index
        out[(size_t)BB * TT + b] = bvv;
        g_btag[b] = bi;
    }
    // zero tail
    for (int t = len + tid; t < TT; t += 256)
        out[(size_t)b * TT + t] = 0.0f;
}

// ---------------- kernel D: equality-match backtrace, 8-deep prefetch ----------------
#define BT_SMEM 65536

__global__ __launch_bounds__(256, 1)
void viterbi_bt(const float* __restrict__ trans, float* __restrict__ out)
{
    extern __shared__ float ts[];   // NN*NN
    const int tid = threadIdx.x;
    for (int idx = tid; idx < NN * NN; idx += 256) ts[idx] = trans[idx];
    __syncthreads();

    const int wid = tid >> 5, lane = tid & 31;
    const int b = blockIdx.x * 8 + wid;
    const int len = g_len[b];
    int cur = g_btag[b];
    float* po = out + (size_t)b * TT;

    for (int t = len + lane; t < TT; t += 32) po[t] = 0.0f;

    const float4* Ab = (const float4*)(g_alpha + (size_t)b * TT * NN);
    const float4* Mb = (const float4*)(g_mv    + (size_t)b * TT * NN);

    int t = len - 1;
    float4 A[8], M[8];
    #pragma unroll
    for (int d = 0; d < 8; ++d) {
        int r = max(t - d, 0);
        A[d] = Ab[(size_t)r * 32 + lane];
        M[d] = Mb[(size_t)r * 32 + lane];
    }

#define BT_STEP(AA, MM)                                                     \
    {                                                                        \
        if (lane == 0) po[t] = (float)cur;                                   \
        float t01 = (cur & 1) ? MM.y : MM.x;                                 \
        float t23 = (cur & 1) ? MM.w : MM.z;                                 \
        float tgt = (cur & 2) ? t23 : t01;                                   \
        tgt = __shfl_sync(0xffffffffu, tgt, cur >> 2);                       \
        float4 trow = *(const float4*)(ts + cur * NN + lane * 4);            \
        unsigned lp = 0xffffffffu;                                           \
        if (AA.w + trow.w == tgt) lp = 4u * lane + 3u;                       \
        if (AA.z + trow.z == tgt) lp = 4u * lane + 2u;                       \
        if (AA.y + trow.y == tgt) lp = 4u * lane + 1u;                       \
        if (AA.x + trow.x == tgt) lp = 4u * lane + 0u;                       \
        cur = (int)(__reduce_min_sync(0xffffffffu, lp) & 127u);              \
        int rl = max(t - 8, 0);                                              \
        AA = Ab[(size_t)rl * 32 + lane]; MM = Mb[(size_t)rl * 32 + lane];    \
        --t;                                                                 \
    }

    while (t >= 1) {
        #pragma unroll
        for (int d = 0; d < 8; ++d) {
            BT_STEP(A[d], M[d]);
            if (t < 1) break;
        }
    }
    if (lane == 0) po[0] = (float)cur;
#undef BT_STEP
}

extern "C" void kernel_launch(void* const* d_in, const int* in_sizes, int n_in,
                              void* d_out, int out_size)
{
    const float* unaries = (const float*)d_in[0];
    const float* trans   = (const float*)d_in[1];
    const void*  lengths = d_in[2];
    float* out = (float*)d_out;

    prep_assign<<<1, 256>>>(lengths);
    softmax_pre<<<BB * TT / 8, 256>>>(unaries);
    cudaFuncSetAttribute(viterbi_fwd,
                         cudaFuncAttributeMaxDynamicSharedMemorySize, FW_SMEM);
    viterbi_fwd<<<BB, 256, FW_SMEM>>>(unaries, trans, out);
    cudaFuncSetAttribute(viterbi_bt,
                         cudaFuncAttributeMaxDynamicSharedMemorySize, BT_SMEM);
    viterbi_bt<<<BB / 8, 256, BT_SMEM>>>(trans, out);
}

// round 9
// speedup vs baseline: 1.5457x; 1.5457x over previous
#include <cuda_runtime.h>
#include <math.h>

#define BB 256
#define TT 512
#define NN 128
#define GO_IDX 1
#define EOS_IDX 2
#define NEGV -10000.0f
#define NSM 148

__device__ int g_assign[BB];
__device__ int g_len[BB];

// ---------------- kernel B: lengths + LPT pairing ----------------
__global__ __launch_bounds__(256)
void prep_assign(const void* __restrict__ lengths_raw)
{
    __shared__ long long key[BB];
    int tid = threadIdx.x;
    const int* li = (const int*)lengths_raw;
    int len = (li[1] == 0) ? (int)(((const long long*)lengths_raw)[tid]) : li[tid];
    len = max(1, min(TT, len));
    g_len[tid] = len;
    key[tid] = ((long long)len << 32) | (long long)tid;
    __syncthreads();
    for (int k = 2; k <= BB; k <<= 1) {
        for (int jj = k >> 1; jj > 0; jj >>= 1) {
            int ixj = tid ^ jj;
            if (ixj > tid) {
                long long a = key[tid], c = key[ixj];
                bool desc = ((tid & k) == 0);
                if (desc ? (a < c) : (a > c)) { key[tid] = c; key[ixj] = a; }
            }
            __syncthreads();
        }
    }
    int rank = (tid < NSM) ? tid : (NSM + BB - 1 - tid);
    rank = min(BB - 1, max(0, rank));
    g_assign[tid] = (int)(key[rank] & 0xffffffffLL);
}

// ---------------- kernel C: integrated DP, lane-adjacent halves, 1 barrier ----------------
// smem: bp 65536 (trans staging first) | mls 4096 | bufA 512 | bufB 512 | termv 512
#define SMEM_BYTES (65536 + 4096 + 512 + 512 + 512)

__global__ __launch_bounds__(256, 2)
void viterbi6(const float* __restrict__ unaries,
              const float* __restrict__ trans,
              float* __restrict__ out)
{
    extern __shared__ unsigned char smem[];
    unsigned char* bp = smem;                        // TT*NN (trans staging first)
    float2* mlsS = (float2*)(smem + 65536);          // TT
    float*  bufA = (float*)(smem + 65536 + 4096);    // NN
    float*  bufB = bufA + NN;                        // NN
    float*  termv = bufB + NN;                       // NN

    int b = g_assign[blockIdx.x];
    b = min(BB - 1, max(0, b));
    const int tid  = threadIdx.x;
    const int j    = tid >> 1;          // cur tag
    const int h    = tid & 1;           // prev half (lane-adjacent pair)
    const int lane = tid & 31;
    const int wrp  = tid >> 5;
    const int len  = g_len[b];

    // stage trans coalesced into smem (region later reused as bp)
    float* ts = (float*)bp;
    for (int idx = tid; idx < NN * NN; idx += 256) ts[idx] = trans[idx];
    if (tid < NN) bufA[tid] = (tid == GO_IDX) ? 0.0f : NEGV;  // exact log_softmax identity
    __syncthreads();

    // pull my 64 trans entries into registers
    float tr[64];
    {
        const float4* base = (const float4*)(ts + j * NN + (h << 6));
        #pragma unroll
        for (int k = 0; k < 16; ++k) {
            float4 v = base[k];
            tr[4*k+0] = v.x; tr[4*k+1] = v.y; tr[4*k+2] = v.z; tr[4*k+3] = v.w;
        }
    }

    const float* ub = unaries + (size_t)b * TT * NN;

    // inline per-row softmax stats: warp w handles rows w, w+8, ...
    for (int t = wrp; t < len; t += 8) {
        float4 x = ((const float4*)(ub + t * NN))[lane];
        float m = fmaxf(fmaxf(x.x, x.y), fmaxf(x.z, x.w));
        #pragma unroll
        for (int o = 16; o > 0; o >>= 1) m = fmaxf(m, __shfl_xor_sync(0xffffffffu, m, o));
        float e = expf(x.x - m) + expf(x.y - m) + expf(x.z - m) + expf(x.w - m);
        #pragma unroll
        for (int o = 16; o > 0; o >>= 1) e += __shfl_xor_sync(0xffffffffu, e, o);
        if (lane == 0) mlsS[t] = make_float2(m, logf(e));
    }
    __syncthreads();   // ts regs read + mls ready (before bp overwrites ts region)

    const float* ap = (h ? (bufA + 64) : bufA);  // adjusted each iter via rd offset
    const float BIG = -3.402823466e38f;
    float ucur = ub[j];                          // both lanes of pair load same addr (merged)

    float* rd = bufA;
    float* wr = bufB;

    for (int t = 0; t < len; ++t) {
        float unext = (t + 1 < len) ? ub[(t + 1) * NN + j] : 0.0f;

        const float4* ap4 = (const float4*)(rd + (h << 6));
        // 8 independent argmax chains over blocks of 8 prev (local 0..63)
        float mv[8]; int mi[8];
        #pragma unroll
        for (int c = 0; c < 8; ++c) { mv[c] = BIG; mi[c] = c * 8; }
        #pragma unroll
        for (int k = 0; k < 16; ++k) {
            float4 a4 = ap4[k];                    // broadcast-pair LDS.128
            const int c = k >> 1;
            const int p = k * 4;
            float v0 = a4.x + tr[p+0];
            float v1 = a4.y + tr[p+1];
            float v2 = a4.z + tr[p+2];
            float v3 = a4.w + tr[p+3];
            if (v0 > mv[c]) { mv[c] = v0; mi[c] = p+0; }
            if (v1 > mv[c]) { mv[c] = v1; mi[c] = p+1; }
            if (v2 > mv[c]) { mv[c] = v2; mi[c] = p+2; }
            if (v3 > mv[c]) { mv[c] = v3; mi[c] = p+3; }
        }
        float bv = mv[0]; int bi = mi[0];
        #pragma unroll
        for (int c = 1; c < 8; ++c)
            if (mv[c] > bv) { bv = mv[c]; bi = mi[c]; }   // ordered blocks: first index
        bi += (h << 6);                                    // global prev index

        // cross-half combine with neighbor lane; first-index tie rule
        float ov = __shfl_xor_sync(0xffffffffu, bv, 1);
        int   oi = __shfl_xor_sync(0xffffffffu, bi, 1);
        if (ov > bv || (ov == bv && oi < bi)) { bv = ov; bi = oi; }

        if (h == 0) {
            float2 c2 = mlsS[t];
            wr[j] = bv + ((ucur - c2.x) - c2.y);   // normalized probv, proven op order
            bp[t * NN + j] = (unsigned char)bi;
        }
        ucur = unext;
        float* tmp = rd; rd = wr; wr = tmp;
        __syncthreads();
    }

    // terminal + backtrace (trans row from gmem; ts smem is now bp)
    if (tid < NN) termv[tid] = rd[tid] + trans[EOS_IDX * NN + tid];
    __syncthreads();

    if (tid == 0) {
        float bvv = termv[0]; int bi = 0;
        #pragma unroll 4
        for (int p = 1; p < NN; ++p)
            if (termv[p] > bvv) { bvv = termv[p]; bi = p; }  // strict > : first index
        out[(size_t)BB * TT + b] = bvv;
        int cur = bi;
        float* po = out + (size_t)b * TT;
        for (int t = len - 1; t >= 0; --t) {
            po[t] = (float)cur;
            if (t > 0) cur = bp[t * NN + cur];
        }
    }
    // zero tail (t >= len)
    for (int t = len + tid; t < TT; t += 256)
        out[(size_t)b * TT + t] = 0.0f;
}

extern "C" void kernel_launch(void* const* d_in, const int* in_sizes, int n_in,
                              void* d_out, int out_size)
{
    const float* unaries = (const float*)d_in[0];
    const float* trans   = (const float*)d_in[1];
    const void*  lengths = d_in[2];
    float* out = (float*)d_out;

    prep_assign<<<1, 256>>>(lengths);
    cudaFuncSetAttribute(viterbi6,
                         cudaFuncAttributeMaxDynamicSharedMemorySize, SMEM_BYTES);
    viterbi6<<<BB, 256, SMEM_BYTES>>>(unaries, trans, out);
}